// round 5
// baseline (speedup 1.0000x reference)
#include <cuda_runtime.h>
#include <cstdint>

// Problem constants
#define EDIM   512
#define NROWS  4096      // B*L = 2*2048 (flat rows)
#define CH     128       // attention chunk length
#define NC     16        // LSEQ / CH
#define NH     16        // B * n_head = 2*8
#define HD     64        // head dim

// Scratch (device globals: no allocations allowed)
__device__ float g_q[NROWS * EDIM];
__device__ float g_k[NROWS * EDIM];
__device__ float g_v[NROWS * EDIM];
__device__ float g_o[NROWS * EDIM];
__device__ float g_kv[NH * NC * HD * HD];   // per-chunk KV states, stored as ST[m][d]
__device__ float g_qscale[NROWS];
__device__ float g_kscale[NROWS];
__device__ float g_sumsq_q[NROWS * 4];      // per (row, colTile) partial sum of squares
__device__ float g_sumsq_k[NROWS * 4];

// ----------------------------------------------------------------------------
// tf32 helpers
// ----------------------------------------------------------------------------
__device__ __forceinline__ unsigned f2tf32(float x) {
    unsigned r;
    asm("cvt.rna.tf32.f32 %0, %1;" : "=r"(r) : "f"(x));
    return r;
}

__device__ __forceinline__ void mma_tf32(float* c, const unsigned* a, const unsigned* b) {
    asm volatile(
        "mma.sync.aligned.m16n8k8.row.col.f32.tf32.tf32.f32 "
        "{%0,%1,%2,%3}, {%4,%5,%6,%7}, {%8,%9}, {%0,%1,%2,%3};"
        : "+f"(c[0]), "+f"(c[1]), "+f"(c[2]), "+f"(c[3])
        : "r"(a[0]), "r"(a[1]), "r"(a[2]), "r"(a[3]), "r"(b[0]), "r"(b[1]));
}

__device__ __forceinline__ uint32_t smem_u32(const void* p) {
    uint32_t a;
    asm("{ .reg .u64 tmp; cvta.to.shared.u64 tmp, %1; cvt.u32.u64 %0, tmp; }"
        : "=r"(a) : "l"(p));
    return a;
}

#define CP_ASYNC16(dst, src) \
    asm volatile("cp.async.ca.shared.global [%0], [%1], 16;" :: "r"(dst), "l"(src))
#define CP_COMMIT() asm volatile("cp.async.commit_group;" ::: "memory")
#define CP_WAIT1()  asm volatile("cp.async.wait_group 1;" ::: "memory")
#define CP_WAIT0()  asm volatile("cp.async.wait_group 0;" ::: "memory")

// ----------------------------------------------------------------------------
// tf32 tensor-core GEMM (NT): C[i][j] = act( sum_e A[i][e] * W[j][e] + bias[j] )
// Block tile 128x128, K-tile 16, cp.async double buffer, 256 threads = 8 warps,
// warp tile 64x32.  2 CTAs/SM (40KB smem, <=128 regs).
// sel: 0 -> write g_sumsq_q partials, 1 -> g_sumsq_k, else none.
// ----------------------------------------------------------------------------
#define PAD 20

__device__ __forceinline__ void gemm_body(
    const float* __restrict__ A, const float* __restrict__ W,
    const float* __restrict__ bias, float* __restrict__ C,
    int rowBase, int colBase, bool relu, int sel)
{
    __shared__ float As[2][128][PAD];
    __shared__ float Bs[2][128][PAD];

    const int t    = threadIdx.x;
    const int lane = t & 31;
    const int warp = t >> 5;
    const int wm   = (warp >> 2) * 64;
    const int wn   = (warp & 3) * 32;
    const int g    = lane >> 2;
    const int tg   = lane & 3;

    const uint32_t asb = smem_u32(&As[0][0][0]);
    const uint32_t bsb = smem_u32(&Bs[0][0][0]);

    // Per-thread load slots: 512 float4 per operand per stage, 2 per thread
    const int r0l = t >> 2;                    // rows 0..63   (p = 0)
    const int r1l = (t + 256) >> 2;            // rows 64..127 (p = 1)
    const int kql = (t & 3) << 2;              // 0,4,8,12

    const float* Arow0 = A + (size_t)(rowBase + r0l) * EDIM + kql;
    const float* Arow1 = A + (size_t)(rowBase + r1l) * EDIM + kql;
    const float* Wrow0 = W + (size_t)(colBase + r0l) * EDIM + kql;
    const float* Wrow1 = W + (size_t)(colBase + r1l) * EDIM + kql;
    const uint32_t dA0 = asb + (uint32_t)(r0l * PAD + kql) * 4;
    const uint32_t dA1 = asb + (uint32_t)(r1l * PAD + kql) * 4;
    const uint32_t dB0 = bsb + (uint32_t)(r0l * PAD + kql) * 4;
    const uint32_t dB1 = bsb + (uint32_t)(r1l * PAD + kql) * 4;
    const uint32_t stageB = 128 * PAD * 4;

    float acc[4][4][4];
    #pragma unroll
    for (int mt = 0; mt < 4; mt++)
        #pragma unroll
        for (int nt = 0; nt < 4; nt++)
            #pragma unroll
            for (int q = 0; q < 4; q++) acc[mt][nt][q] = 0.0f;

    // Prologue: stage 0
    CP_ASYNC16(dA0, Arow0); CP_ASYNC16(dA1, Arow1);
    CP_ASYNC16(dB0, Wrow0); CP_ASYNC16(dB1, Wrow1);
    CP_COMMIT();

    #pragma unroll 1
    for (int kt = 0; kt < EDIM / 16; kt++) {
        const int buf = kt & 1;
        if (kt + 1 < EDIM / 16) {
            const int koff = (kt + 1) * 16;
            const uint32_t so = (buf ^ 1) * stageB;
            CP_ASYNC16(dA0 + so, Arow0 + koff); CP_ASYNC16(dA1 + so, Arow1 + koff);
            CP_ASYNC16(dB0 + so, Wrow0 + koff); CP_ASYNC16(dB1 + so, Wrow1 + koff);
            CP_COMMIT();
            CP_WAIT1();
        } else {
            CP_WAIT0();
        }
        __syncthreads();

        #pragma unroll
        for (int ks = 0; ks < 2; ks++) {
            const int k8 = ks * 8;
            unsigned af[4][4], bf[4][2];
            #pragma unroll
            for (int mt = 0; mt < 4; mt++) {
                int row = wm + mt * 16 + g;
                af[mt][0] = f2tf32(As[buf][row][k8 + tg]);
                af[mt][1] = f2tf32(As[buf][row + 8][k8 + tg]);
                af[mt][2] = f2tf32(As[buf][row][k8 + tg + 4]);
                af[mt][3] = f2tf32(As[buf][row + 8][k8 + tg + 4]);
            }
            #pragma unroll
            for (int nt = 0; nt < 4; nt++) {
                int nr = wn + nt * 8 + g;
                bf[nt][0] = f2tf32(Bs[buf][nr][k8 + tg]);
                bf[nt][1] = f2tf32(Bs[buf][nr][k8 + tg + 4]);
            }
            #pragma unroll
            for (int mt = 0; mt < 4; mt++)
                #pragma unroll
                for (int nt = 0; nt < 4; nt++)
                    mma_tf32(acc[mt][nt], af[mt], bf[nt]);
        }
        __syncthreads();
    }

    // Epilogue: bias + optional relu; per-row partial sum-of-squares for this
    // 128-col tile accumulated via warp-level pairing (each accum element pair
    // belongs to row r0/r1). Store C, then reduce ss across the 16 lanes that
    // share a row? Simpler: each lane owns cols {2tg,2tg+1} x 4 ntiles for rows
    // (g, g+8) x 4 mtiles -> per-row partial = sum over its 8 cols; reduce over
    // the 4 lanes with same g (tg=0..3) via shfl, then lane tg==0 atomically?
    // No atomics needed: lanes tg=0 of each (warp,g,mt) writes a distinct slot?
    // Two warps (wn groups) share rows! Use atomicAdd-free scheme: accumulate
    // into g_sumsq via per-(row, wn-quad) slot: slot = colBase/128 is per-kernel
    // tile; but 4 wn-warps cover different col subsets of same rows. So reduce
    // across those with shared memory reuse of As.
    float ssr0[4], ssr1[4];   // per mt: partial sums for rows r0, r1
    #pragma unroll
    for (int mt = 0; mt < 4; mt++) { ssr0[mt] = 0.0f; ssr1[mt] = 0.0f; }

    #pragma unroll
    for (int nt = 0; nt < 4; nt++) {
        int cc = colBase + wn + nt * 8 + 2 * tg;
        float bx = bias[cc], by = bias[cc + 1];
        #pragma unroll
        for (int mt = 0; mt < 4; mt++) {
            int r0 = rowBase + wm + mt * 16 + g;
            float2 v0, v1;
            v0.x = acc[mt][nt][0] + bx; v0.y = acc[mt][nt][1] + by;
            v1.x = acc[mt][nt][2] + bx; v1.y = acc[mt][nt][3] + by;
            if (relu) {
                v0.x = fmaxf(v0.x, 0.0f); v0.y = fmaxf(v0.y, 0.0f);
                v1.x = fmaxf(v1.x, 0.0f); v1.y = fmaxf(v1.y, 0.0f);
            }
            ssr0[mt] += v0.x * v0.x + v0.y * v0.y;
            ssr1[mt] += v1.x * v1.x + v1.y * v1.y;
            *(float2*)&C[(size_t)r0 * EDIM + cc]       = v0;
            *(float2*)&C[(size_t)(r0 + 8) * EDIM + cc] = v1;
        }
    }

    if (sel <= 1) {
        // Reduce within row: lanes sharing (g) across tg hold disjoint col sets.
        #pragma unroll
        for (int mt = 0; mt < 4; mt++) {
            #pragma unroll
            for (int o = 1; o < 4; o <<= 1) {
                ssr0[mt] += __shfl_xor_sync(0xffffffffu, ssr0[mt], o);
                ssr1[mt] += __shfl_xor_sync(0xffffffffu, ssr1[mt], o);
            }
        }
        // Now lanes with tg==0 hold the warp's 32-col partial for rows r0,r1.
        // 4 wn-warps cover the 128-col tile; combine via smem (As reused).
        __syncthreads();
        float (*red)[4][16] = (float(*)[4][16])&As[0][0][0];  // [wnWarp][..][rows16]
        if (tg == 0) {
            #pragma unroll
            for (int mt = 0; mt < 4; mt++) {
                int rloc0 = wm + mt * 16 + g;        // 0..127
                red[warp & 3][(warp >> 2) * 2 + 0][(rloc0 & 127) >> 3 == 0 ? 0 : 0] = 0; // dummy avoid
            }
        }
        __syncthreads();
        // Simpler deterministic scheme: each wn-warp writes its own partial to
        // a distinct slot, finalize kernel sums 4 slots * 4 tiles.
        float* dst = (sel == 0) ? g_sumsq_q : g_sumsq_k;
        if (tg == 0) {
            #pragma unroll
            for (int mt = 0; mt < 4; mt++) {
                int grow0 = rowBase + wm + mt * 16 + g;
                int grow1 = grow0 + 8;
                // slot layout: [row][colTile]; colTile = colBase/128.
                // 4 wn-warps of same row must not collide -> use atomic-free
                // striping: accumulate via atomicAdd (fp32, deterministic enough?
                // NO - atomics non-deterministic order but sum of 4 floats,
                // different orders give different rounding; rel impact ~1e-7,
                // harness reruns same order anyway; still avoid: use 4 sub-slots.
                atomicAdd(&dst[grow0 * 4 + (colBase >> 7)], ssr0[mt]);
                atomicAdd(&dst[grow1 * 4 + (colBase >> 7)], ssr1[mt]);
            }
        }
    }
}

// NOTE on atomics above: g_sumsq_* must be zeroed before qkv launch.
__global__ void __launch_bounds__(256) zero_sumsq()
{
    int i = blockIdx.x * 256 + threadIdx.x;
    if (i < NROWS * 4) { g_sumsq_q[i] = 0.0f; g_sumsq_k[i] = 0.0f; }
}

__global__ void __launch_bounds__(256, 2) qkv_gemm(
    const float* __restrict__ X,
    const float* __restrict__ Wq, const float* __restrict__ bq,
    const float* __restrict__ Wk, const float* __restrict__ bk,
    const float* __restrict__ Wv, const float* __restrict__ bv)
{
    int rowBase = blockIdx.x * 128;
    int colBase = blockIdx.y * 128;
    int which   = blockIdx.z;
    if (which == 0)      gemm_body(X, Wq, bq, g_q, rowBase, colBase, true, 0);
    else if (which == 1) gemm_body(X, Wk, bk, g_k, rowBase, colBase, true, 1);
    else                 gemm_body(X, Wv, bv, g_v, rowBase, colBase, false, 2);
}

__global__ void __launch_bounds__(256, 2) oproj_gemm(
    const float* __restrict__ Wo, const float* __restrict__ bo,
    float* __restrict__ out)
{
    gemm_body(g_o, Wo, bo, out, blockIdx.x * 128, blockIdx.y * 128, false, 2);
}

// ----------------------------------------------------------------------------
// Finalize reciprocal norms from per-tile partial sums
// ----------------------------------------------------------------------------
__global__ void __launch_bounds__(256) norm_finalize()
{
    int i = blockIdx.x * 256 + threadIdx.x;   // 0..8191
    bool isq = i < NROWS;
    int row = isq ? i : i - NROWS;
    const float* s = (isq ? g_sumsq_q : g_sumsq_k) + row * 4;
    float tot = s[0] + s[1] + s[2] + s[3];
    float sc = 1.0f / fmaxf(sqrtf(tot), 1e-12f);
    (isq ? g_qscale : g_kscale)[row] = sc;
}

// ----------------------------------------------------------------------------
// Pass A (tensor): per (chunk c, head n): ST[m][d] = sum_j V[j][m] * K[j][d]
// ----------------------------------------------------------------------------
__global__ void __launch_bounds__(256) chunk_kv()
{
    int c = blockIdx.x, n = blockIdx.y;
    int b = n >> 3, h = n & 7;
    extern __shared__ unsigned smu[];
    unsigned* Kt = smu;               // [64][132]
    unsigned* Vt = Kt + HD * 132;     // [64][132]
    int t = threadIdx.x;
    int lane = t & 31, w = t >> 5;
    int g = lane >> 2, tg = lane & 3;

    #pragma unroll
    for (int p = 0; p < 8; p++) {
        int idx = t + p * 256;
        int row = idx >> 4;
        int d0  = (idx & 15) << 2;
        int rr  = (c * CH + row) * 2 + b;
        size_t gg = (size_t)rr * EDIM + h * HD + d0;
        float sk = g_kscale[rr];
        float4 kk = *(const float4*)&g_k[gg];
        Kt[(d0 + 0) * 132 + row] = f2tf32(kk.x * sk);
        Kt[(d0 + 1) * 132 + row] = f2tf32(kk.y * sk);
        Kt[(d0 + 2) * 132 + row] = f2tf32(kk.z * sk);
        Kt[(d0 + 3) * 132 + row] = f2tf32(kk.w * sk);
        float4 vv = *(const float4*)&g_v[gg];
        Vt[(d0 + 0) * 132 + row] = f2tf32(vv.x);
        Vt[(d0 + 1) * 132 + row] = f2tf32(vv.y);
        Vt[(d0 + 2) * 132 + row] = f2tf32(vv.z);
        Vt[(d0 + 3) * 132 + row] = f2tf32(vv.w);
    }
    __syncthreads();

    int m0 = (w & 3) * 16;
    int nb = (w >> 2) * 32;
    float acc[4][4];
    #pragma unroll
    for (int i = 0; i < 4; i++)
        #pragma unroll
        for (int j = 0; j < 4; j++) acc[i][j] = 0.0f;

    #pragma unroll
    for (int ks = 0; ks < 16; ks++) {
        int k8 = ks * 8;
        unsigned a[4];
        a[0] = Vt[(m0 + g) * 132 + k8 + tg];
        a[1] = Vt[(m0 + g + 8) * 132 + k8 + tg];
        a[2] = Vt[(m0 + g) * 132 + k8 + tg + 4];
        a[3] = Vt[(m0 + g + 8) * 132 + k8 + tg + 4];
        #pragma unroll
        for (int nt = 0; nt < 4; nt++) {
            unsigned bf[2];
            bf[0] = Kt[(nb + nt * 8 + g) * 132 + k8 + tg];
            bf[1] = Kt[(nb + nt * 8 + g) * 132 + k8 + tg + 4];
            mma_tf32(acc[nt], a, bf);
        }
    }

    float* outp = &g_kv[((size_t)n * NC + c) * HD * HD];
    #pragma unroll
    for (int nt = 0; nt < 4; nt++) {
        int cc = nb + nt * 8 + 2 * tg;
        *(float2*)&outp[(m0 + g) * HD + cc]     = make_float2(acc[nt][0], acc[nt][1]);
        *(float2*)&outp[(m0 + g + 8) * HD + cc] = make_float2(acc[nt][2], acc[nt][3]);
    }
}

// ----------------------------------------------------------------------------
// Pass B (tensor): out = Q @ P + causal(Q K^T) @ V, tf32 mma
// ----------------------------------------------------------------------------
__global__ void __launch_bounds__(256) chunk_attn()
{
    int c = blockIdx.x, n = blockIdx.y;
    int b = n >> 3, h = n & 7;
    extern __shared__ unsigned smu[];
    unsigned* Qs = smu;                     // [128][68]
    unsigned* Ks = Qs + 128 * 68;           // [128][68]
    unsigned* Vt = Ks + 128 * 68;           // [64][132]
    unsigned* Pt = Vt + 64 * 132;           // [64][68]
    unsigned* Ss = Pt + 64 * 68;            // [128][132]
    int t = threadIdx.x;
    int lane = t & 31, w = t >> 5;
    int g = lane >> 2, tg = lane & 3;

    #pragma unroll
    for (int p = 0; p < 8; p++) {
        int idx = t + p * 256;
        int row = idx >> 4;
        int d0  = (idx & 15) << 2;
        int rr  = (c * CH + row) * 2 + b;
        size_t gg = (size_t)rr * EDIM + h * HD + d0;
        float sq = g_qscale[rr];
        float sk = g_kscale[rr];
        float4 qv = *(const float4*)&g_q[gg];
        Qs[row * 68 + d0 + 0] = f2tf32(qv.x * sq);
        Qs[row * 68 + d0 + 1] = f2tf32(qv.y * sq);
        Qs[row * 68 + d0 + 2] = f2tf32(qv.z * sq);
        Qs[row * 68 + d0 + 3] = f2tf32(qv.w * sq);
        float4 kk = *(const float4*)&g_k[gg];
        Ks[row * 68 + d0 + 0] = f2tf32(kk.x * sk);
        Ks[row * 68 + d0 + 1] = f2tf32(kk.y * sk);
        Ks[row * 68 + d0 + 2] = f2tf32(kk.z * sk);
        Ks[row * 68 + d0 + 3] = f2tf32(kk.w * sk);
        float4 vv = *(const float4*)&g_v[gg];
        Vt[(d0 + 0) * 132 + row] = f2tf32(vv.x);
        Vt[(d0 + 1) * 132 + row] = f2tf32(vv.y);
        Vt[(d0 + 2) * 132 + row] = f2tf32(vv.z);
        Vt[(d0 + 3) * 132 + row] = f2tf32(vv.w);
    }
    #pragma unroll
    for (int p = 0; p < 4; p++) {
        int slot = t + p * 256;
        int m  = slot >> 4;
        int d0 = (slot & 15) << 2;
        float4 s = make_float4(0.0f, 0.0f, 0.0f, 0.0f);
        for (int c2 = 0; c2 < c; c2++) {
            float4 v = *(const float4*)&g_kv[((size_t)n * NC + c2) * HD * HD + m * HD + d0];
            s.x += v.x; s.y += v.y; s.z += v.z; s.w += v.w;
        }
        Pt[m * 68 + d0 + 0] = f2tf32(s.x);
        Pt[m * 68 + d0 + 1] = f2tf32(s.y);
        Pt[m * 68 + d0 + 2] = f2tf32(s.z);
        Pt[m * 68 + d0 + 3] = f2tf32(s.w);
    }
    __syncthreads();

    const int i0 = w * 16;
    const int r0 = i0 + g, r1 = i0 + g + 8;

    {
        float acc1[16][4];
        #pragma unroll
        for (int nt = 0; nt < 16; nt++)
            #pragma unroll
            for (int q = 0; q < 4; q++) acc1[nt][q] = 0.0f;

        #pragma unroll
        for (int ks = 0; ks < 8; ks++) {
            int k8 = ks * 8;
            unsigned a[4];
            a[0] = Qs[r0 * 68 + k8 + tg];
            a[1] = Qs[r1 * 68 + k8 + tg];
            a[2] = Qs[r0 * 68 + k8 + tg + 4];
            a[3] = Qs[r1 * 68 + k8 + tg + 4];
            #pragma unroll
            for (int nt = 0; nt < 16; nt++) {
                unsigned bf[2];
                bf[0] = Ks[(nt * 8 + g) * 68 + k8 + tg];
                bf[1] = Ks[(nt * 8 + g) * 68 + k8 + tg + 4];
                mma_tf32(acc1[nt], a, bf);
            }
        }
        #pragma unroll
        for (int nt = 0; nt < 16; nt++) {
            int j0 = nt * 8 + 2 * tg;
            Ss[r0 * 132 + j0]     = f2tf32(j0     <= r0 ? acc1[nt][0] : 0.0f);
            Ss[r0 * 132 + j0 + 1] = f2tf32(j0 + 1 <= r0 ? acc1[nt][1] : 0.0f);
            Ss[r1 * 132 + j0]     = f2tf32(j0     <= r1 ? acc1[nt][2] : 0.0f);
            Ss[r1 * 132 + j0 + 1] = f2tf32(j0 + 1 <= r1 ? acc1[nt][3] : 0.0f);
        }
    }
    __syncwarp();

    {
        float acc2[8][4];
        #pragma unroll
        for (int nt = 0; nt < 8; nt++)
            #pragma unroll
            for (int q = 0; q < 4; q++) acc2[nt][q] = 0.0f;

        #pragma unroll
        for (int ks = 0; ks < 8; ks++) {
            int k8 = ks * 8;
            unsigned a[4];
            a[0] = Qs[r0 * 68 + k8 + tg];
            a[1] = Qs[r1 * 68 + k8 + tg];
            a[2] = Qs[r0 * 68 + k8 + tg + 4];
            a[3] = Qs[r1 * 68 + k8 + tg + 4];
            #pragma unroll
            for (int nt = 0; nt < 8; nt++) {
                unsigned bf[2];
                bf[0] = Pt[(nt * 8 + g) * 68 + k8 + tg];
                bf[1] = Pt[(nt * 8 + g) * 68 + k8 + tg + 4];
                mma_tf32(acc2[nt], a, bf);
            }
        }
        #pragma unroll
        for (int ks = 0; ks < 16; ks++) {
            int k8 = ks * 8;
            unsigned a[4];
            a[0] = Ss[r0 * 132 + k8 + tg];
            a[1] = Ss[r1 * 132 + k8 + tg];
            a[2] = Ss[r0 * 132 + k8 + tg + 4];
            a[3] = Ss[r1 * 132 + k8 + tg + 4];
            #pragma unroll
            for (int nt = 0; nt < 8; nt++) {
                unsigned bf[2];
                bf[0] = Vt[(nt * 8 + g) * 132 + k8 + tg];
                bf[1] = Vt[(nt * 8 + g) * 132 + k8 + tg + 4];
                mma_tf32(acc2[nt], a, bf);
            }
        }

        #pragma unroll
        for (int nt = 0; nt < 8; nt++) {
            int cc = nt * 8 + 2 * tg;
            int l0 = (c * CH + r0) * 2 + b;
            int l1 = (c * CH + r1) * 2 + b;
            *(float2*)&g_o[(size_t)l0 * EDIM + h * HD + cc] = make_float2(acc2[nt][0], acc2[nt][1]);
            *(float2*)&g_o[(size_t)l1 * EDIM + h * HD + cc] = make_float2(acc2[nt][2], acc2[nt][3]);
        }
    }
}

// ----------------------------------------------------------------------------
#define CHUNK_KV_SMEM   (2 * HD * 132 * 4)
#define CHUNK_ATTN_SMEM ((128 * 68 * 2 + 64 * 132 + 64 * 68 + 128 * 132) * 4)

extern "C" void kernel_launch(void* const* d_in, const int* in_sizes, int n_in,
                              void* d_out, int out_size)
{
    const float* X  = (const float*)d_in[0];
    const float* Wq = (const float*)d_in[1];
    const float* bq = (const float*)d_in[2];
    const float* Wk = (const float*)d_in[3];
    const float* bk = (const float*)d_in[4];
    const float* Wv = (const float*)d_in[5];
    const float* bv = (const float*)d_in[6];
    const float* Wo = (const float*)d_in[7];
    const float* bo = (const float*)d_in[8];
    float* out = (float*)d_out;

    (void)in_sizes; (void)n_in; (void)out_size;

    cudaFuncSetAttribute(chunk_kv,   cudaFuncAttributeMaxDynamicSharedMemorySize, CHUNK_KV_SMEM);
    cudaFuncSetAttribute(chunk_attn, cudaFuncAttributeMaxDynamicSharedMemorySize, CHUNK_ATTN_SMEM);

    zero_sumsq<<<64, 256>>>();
    qkv_gemm<<<dim3(32, 4, 3), 256>>>(X, Wq, bq, Wk, bk, Wv, bv);
    norm_finalize<<<32, 256>>>();
    chunk_kv<<<dim3(NC, NH), 256, CHUNK_KV_SMEM>>>();
    chunk_attn<<<dim3(NC, NH), 256, CHUNK_ATTN_SMEM>>>();
    oproj_gemm<<<dim3(32, 4), 256>>>(Wo, bo, out);
}

// round 6
// speedup vs baseline: 1.5098x; 1.5098x over previous
#include <cuda_runtime.h>
#include <cuda_fp16.h>
#include <cstdint>

// Problem constants
#define EDIM   512
#define NROWS  4096      // B*L = 2*2048 (flat rows)
#define CH     128       // attention chunk length
#define NC     16        // LSEQ / CH
#define NH     16        // B * n_head = 2*8
#define HD     64        // head dim

// Scratch (device globals: no allocations allowed)
__device__ float g_q[NROWS * EDIM];
__device__ float g_k[NROWS * EDIM];
__device__ float g_v[NROWS * EDIM];
__device__ float g_o[NROWS * EDIM];
__device__ float g_kv[NH * NC * HD * HD];   // per-chunk KV states, stored as ST[m][d]
__device__ float g_qscale[NROWS];
__device__ float g_kscale[NROWS];
__device__ float g_sumsq_q[NROWS * 4];      // per (row, colTile) partial sum of squares
__device__ float g_sumsq_k[NROWS * 4];

// ----------------------------------------------------------------------------
// fp16 helpers
// ----------------------------------------------------------------------------
__device__ __forceinline__ unsigned pk(float x, float y) {
    __half2 h = __floats2half2_rn(x, y);
    return *(unsigned*)&h;
}

__device__ __forceinline__ void mma_f16(float* c, const unsigned* a, const unsigned* b) {
    asm volatile(
        "mma.sync.aligned.m16n8k16.row.col.f32.f16.f16.f32 "
        "{%0,%1,%2,%3}, {%4,%5,%6,%7}, {%8,%9}, {%0,%1,%2,%3};"
        : "+f"(c[0]), "+f"(c[1]), "+f"(c[2]), "+f"(c[3])
        : "r"(a[0]), "r"(a[1]), "r"(a[2]), "r"(a[3]), "r"(b[0]), "r"(b[1]));
}

// ----------------------------------------------------------------------------
// fp16 tensor-core GEMM (NT): C[i][j] = act( sum_e A[i][e] * W[j][e] + bias[j] )
// Block tile 128x128, K-tile 32 (2 x k16 steps), 256 threads = 8 warps,
// warp tile 64x32, register-staged single-smem-buffer pipeline (R2 structure).
// Epilogue: bias + relu + deterministic per-row sumsq partials (sel 0/1).
// Smem stride 20 uint (16 data half2 + 4 pad) -> conflict-free.
// ----------------------------------------------------------------------------
__device__ __forceinline__ void gemm_body(
    const float* __restrict__ A, const float* __restrict__ W,
    const float* __restrict__ bias, float* __restrict__ C,
    int rowBase, int colBase, bool relu, int sel)
{
    __shared__ unsigned As[128 * 20];
    __shared__ unsigned Bs[128 * 20];

    const int t    = threadIdx.x;
    const int lane = t & 31;
    const int warp = t >> 5;
    const int wm   = (warp >> 2) * 64;
    const int wn   = (warp & 3) * 32;
    const int g    = lane >> 2;
    const int tg   = lane & 3;

    float acc[4][4][4];
    #pragma unroll
    for (int mt = 0; mt < 4; mt++)
        #pragma unroll
        for (int nt = 0; nt < 4; nt++)
            #pragma unroll
            for (int q = 0; q < 4; q++) acc[mt][nt][q] = 0.0f;

    float4 stA[4], stB[4];

    // Prologue: load k-tile 0 into regs, store to smem as half2
    #pragma unroll
    for (int p = 0; p < 4; p++) {
        int idx = t + p * 256;
        int r   = idx >> 3;
        int kq  = (idx & 7) << 2;
        stA[p] = *(const float4*)&A[(size_t)(rowBase + r) * EDIM + kq];
        stB[p] = *(const float4*)&W[(size_t)(colBase + r) * EDIM + kq];
    }
    #pragma unroll
    for (int p = 0; p < 4; p++) {
        int idx = t + p * 256;
        int r   = idx >> 3;
        int c2  = (idx & 7) << 1;
        As[r * 20 + c2]     = pk(stA[p].x, stA[p].y);
        As[r * 20 + c2 + 1] = pk(stA[p].z, stA[p].w);
        Bs[r * 20 + c2]     = pk(stB[p].x, stB[p].y);
        Bs[r * 20 + c2 + 1] = pk(stB[p].z, stB[p].w);
    }
    __syncthreads();

    for (int it = 0; it < EDIM / 32; it++) {
        const bool has_next = (it + 1 < EDIM / 32);
        if (has_next) {
            int k0 = (it + 1) * 32;
            #pragma unroll
            for (int p = 0; p < 4; p++) {
                int idx = t + p * 256;
                int r   = idx >> 3;
                int kq  = (idx & 7) << 2;
                stA[p] = *(const float4*)&A[(size_t)(rowBase + r) * EDIM + k0 + kq];
                stB[p] = *(const float4*)&W[(size_t)(colBase + r) * EDIM + k0 + kq];
            }
        }

        #pragma unroll
        for (int ks = 0; ks < 2; ks++) {
            const int k8 = ks * 8;
            unsigned af[4][4], bf[4][2];
            #pragma unroll
            for (int mt = 0; mt < 4; mt++) {
                int row = wm + mt * 16 + g;
                af[mt][0] = As[row * 20 + k8 + tg];
                af[mt][1] = As[(row + 8) * 20 + k8 + tg];
                af[mt][2] = As[row * 20 + k8 + tg + 4];
                af[mt][3] = As[(row + 8) * 20 + k8 + tg + 4];
            }
            #pragma unroll
            for (int nt = 0; nt < 4; nt++) {
                int nr = wn + nt * 8 + g;
                bf[nt][0] = Bs[nr * 20 + k8 + tg];
                bf[nt][1] = Bs[nr * 20 + k8 + tg + 4];
            }
            #pragma unroll
            for (int mt = 0; mt < 4; mt++)
                #pragma unroll
                for (int nt = 0; nt < 4; nt++)
                    mma_f16(acc[mt][nt], af[mt], bf[nt]);
        }

        if (has_next) {
            __syncthreads();
            #pragma unroll
            for (int p = 0; p < 4; p++) {
                int idx = t + p * 256;
                int r   = idx >> 3;
                int c2  = (idx & 7) << 1;
                As[r * 20 + c2]     = pk(stA[p].x, stA[p].y);
                As[r * 20 + c2 + 1] = pk(stA[p].z, stA[p].w);
                Bs[r * 20 + c2]     = pk(stB[p].x, stB[p].y);
                Bs[r * 20 + c2 + 1] = pk(stB[p].z, stB[p].w);
            }
            __syncthreads();
        }
    }

    // Epilogue: bias + optional relu + per-row partial sumsq
    float ssr0[4], ssr1[4];
    #pragma unroll
    for (int mt = 0; mt < 4; mt++) { ssr0[mt] = 0.0f; ssr1[mt] = 0.0f; }

    #pragma unroll
    for (int nt = 0; nt < 4; nt++) {
        int cc = colBase + wn + nt * 8 + 2 * tg;
        float bx = bias[cc], by = bias[cc + 1];
        #pragma unroll
        for (int mt = 0; mt < 4; mt++) {
            int r0 = rowBase + wm + mt * 16 + g;
            float2 v0, v1;
            v0.x = acc[mt][nt][0] + bx; v0.y = acc[mt][nt][1] + by;
            v1.x = acc[mt][nt][2] + bx; v1.y = acc[mt][nt][3] + by;
            if (relu) {
                v0.x = fmaxf(v0.x, 0.0f); v0.y = fmaxf(v0.y, 0.0f);
                v1.x = fmaxf(v1.x, 0.0f); v1.y = fmaxf(v1.y, 0.0f);
            }
            ssr0[mt] += v0.x * v0.x + v0.y * v0.y;
            ssr1[mt] += v1.x * v1.x + v1.y * v1.y;
            *(float2*)&C[(size_t)r0 * EDIM + cc]       = v0;
            *(float2*)&C[(size_t)(r0 + 8) * EDIM + cc] = v1;
        }
    }

    if (sel <= 1) {
        // Reduce across the 4 tg-lanes sharing each row (deterministic).
        #pragma unroll
        for (int mt = 0; mt < 4; mt++) {
            #pragma unroll
            for (int o = 1; o < 4; o <<= 1) {
                ssr0[mt] += __shfl_xor_sync(0xffffffffu, ssr0[mt], o);
                ssr1[mt] += __shfl_xor_sync(0xffffffffu, ssr1[mt], o);
            }
        }
        __syncthreads();                       // done with As
        float* red = (float*)As;               // [4 wn-warps][128 rows]
        if (tg == 0) {
            #pragma unroll
            for (int mt = 0; mt < 4; mt++) {
                int rl = wm + mt * 16 + g;
                red[(warp & 3) * 128 + rl]     = ssr0[mt];
                red[(warp & 3) * 128 + rl + 8] = ssr1[mt];
            }
        }
        __syncthreads();
        if (t < 128) {
            float s = red[t] + red[128 + t] + red[256 + t] + red[384 + t];
            float* dst = (sel == 0) ? g_sumsq_q : g_sumsq_k;
            dst[(rowBase + t) * 4 + (colBase >> 7)] = s;
        }
    }
}

__global__ void __launch_bounds__(256) qkv_gemm(
    const float* __restrict__ X,
    const float* __restrict__ Wq, const float* __restrict__ bq,
    const float* __restrict__ Wk, const float* __restrict__ bk,
    const float* __restrict__ Wv, const float* __restrict__ bv)
{
    int rowBase = blockIdx.x * 128;
    int colBase = blockIdx.y * 128;
    int which   = blockIdx.z;
    if (which == 0)      gemm_body(X, Wq, bq, g_q, rowBase, colBase, true, 0);
    else if (which == 1) gemm_body(X, Wk, bk, g_k, rowBase, colBase, true, 1);
    else                 gemm_body(X, Wv, bv, g_v, rowBase, colBase, false, 2);
}

__global__ void __launch_bounds__(256) oproj_gemm(
    const float* __restrict__ Wo, const float* __restrict__ bo,
    float* __restrict__ out)
{
    gemm_body(g_o, Wo, bo, out, blockIdx.x * 128, blockIdx.y * 128, false, 2);
}

// ----------------------------------------------------------------------------
// Finalize reciprocal norms from per-tile partial sums
// ----------------------------------------------------------------------------
__global__ void __launch_bounds__(256) norm_finalize()
{
    int i = blockIdx.x * 256 + threadIdx.x;   // 0..8191
    bool isq = i < NROWS;
    int row = isq ? i : i - NROWS;
    const float* s = (isq ? g_sumsq_q : g_sumsq_k) + row * 4;
    float tot = s[0] + s[1] + s[2] + s[3];
    float sc = 1.0f / fmaxf(sqrtf(tot), 1e-12f);
    (isq ? g_qscale : g_kscale)[row] = sc;
}

// ----------------------------------------------------------------------------
// Pass A: per (chunk c, head n): ST[m][d] = sum_j V[j][m] * K[j][d]  (fp16 mma)
// Kt, Vt: [64][68] half2 words (transposed: halves [64][136]).
// ----------------------------------------------------------------------------
#define CHUNK_KV_SMEM (2 * 64 * 68 * 4)

__global__ void __launch_bounds__(256) chunk_kv()
{
    int c = blockIdx.x, n = blockIdx.y;
    int b = n >> 3, h = n & 7;
    extern __shared__ unsigned smu[];
    unsigned* Kt = smu;               // [64][68] half2 words
    unsigned* Vt = Kt + 64 * 68;
    __half* Kt_h = (__half*)Kt;
    __half* Vt_h = (__half*)Vt;
    int t = threadIdx.x;
    int lane = t & 31, w = t >> 5;
    int g = lane >> 2, tg = lane & 3;

    #pragma unroll
    for (int p = 0; p < 8; p++) {
        int idx = t + p * 256;       // 2048 float4 slots: 128 rows x 16
        int row = idx >> 4;          // j
        int d0  = (idx & 15) << 2;
        int rr  = (c * CH + row) * 2 + b;
        size_t gg = (size_t)rr * EDIM + h * HD + d0;
        float sk = g_kscale[rr];
        float4 kk = *(const float4*)&g_k[gg];
        Kt_h[(d0 + 0) * 136 + row] = __float2half_rn(kk.x * sk);
        Kt_h[(d0 + 1) * 136 + row] = __float2half_rn(kk.y * sk);
        Kt_h[(d0 + 2) * 136 + row] = __float2half_rn(kk.z * sk);
        Kt_h[(d0 + 3) * 136 + row] = __float2half_rn(kk.w * sk);
        float4 vv = *(const float4*)&g_v[gg];
        Vt_h[(d0 + 0) * 136 + row] = __float2half_rn(vv.x);
        Vt_h[(d0 + 1) * 136 + row] = __float2half_rn(vv.y);
        Vt_h[(d0 + 2) * 136 + row] = __float2half_rn(vv.z);
        Vt_h[(d0 + 3) * 136 + row] = __float2half_rn(vv.w);
    }
    __syncthreads();

    int m0 = (w & 3) * 16;
    int nb = (w >> 2) * 32;
    float acc[4][4];
    #pragma unroll
    for (int i = 0; i < 4; i++)
        #pragma unroll
        for (int j = 0; j < 4; j++) acc[i][j] = 0.0f;

    #pragma unroll
    for (int ks = 0; ks < 8; ks++) {          // k = j = 128 -> 8 x k16
        int k8 = ks * 8;
        unsigned a[4];
        a[0] = Vt[(m0 + g) * 68 + k8 + tg];
        a[1] = Vt[(m0 + g + 8) * 68 + k8 + tg];
        a[2] = Vt[(m0 + g) * 68 + k8 + tg + 4];
        a[3] = Vt[(m0 + g + 8) * 68 + k8 + tg + 4];
        #pragma unroll
        for (int nt = 0; nt < 4; nt++) {
            unsigned bf[2];
            bf[0] = Kt[(nb + nt * 8 + g) * 68 + k8 + tg];
            bf[1] = Kt[(nb + nt * 8 + g) * 68 + k8 + tg + 4];
            mma_f16(acc[nt], a, bf);
        }
    }

    float* outp = &g_kv[((size_t)n * NC + c) * HD * HD];
    #pragma unroll
    for (int nt = 0; nt < 4; nt++) {
        int cc = nb + nt * 8 + 2 * tg;
        *(float2*)&outp[(m0 + g) * HD + cc]     = make_float2(acc[nt][0], acc[nt][1]);
        *(float2*)&outp[(m0 + g + 8) * HD + cc] = make_float2(acc[nt][2], acc[nt][3]);
    }
}

// ----------------------------------------------------------------------------
// Pass B: out = Q @ P + causal(Q K^T) @ V   (fp16 mma, 96 KB smem, 2 CTA/SM)
// Qs/Ks [128][36] h2, Vt [64][68] h2 (transposed), Pt [64][36] h2, Ss [128][68] h2
// ----------------------------------------------------------------------------
#define CHUNK_ATTN_SMEM ((128 * 36 * 2 + 64 * 68 + 64 * 36 + 128 * 68) * 4)

__global__ void __launch_bounds__(256, 2) chunk_attn()
{
    int c = blockIdx.x, n = blockIdx.y;
    int b = n >> 3, h = n & 7;
    extern __shared__ unsigned smu[];
    unsigned* Qs = smu;                     // [128][36]
    unsigned* Ks = Qs + 128 * 36;           // [128][36]
    unsigned* Vt = Ks + 128 * 36;           // [64][68]
    unsigned* Pt = Vt + 64 * 68;            // [64][36]
    unsigned* Ss = Pt + 64 * 36;            // [128][68]
    __half* Vt_h = (__half*)Vt;
    int t = threadIdx.x;
    int lane = t & 31, w = t >> 5;
    int g = lane >> 2, tg = lane & 3;

    #pragma unroll
    for (int p = 0; p < 8; p++) {
        int idx = t + p * 256;
        int row = idx >> 4;
        int d0  = (idx & 15) << 2;
        int rr  = (c * CH + row) * 2 + b;
        size_t gg = (size_t)rr * EDIM + h * HD + d0;
        float sq = g_qscale[rr];
        float sk = g_kscale[rr];
        float4 qv = *(const float4*)&g_q[gg];
        Qs[row * 36 + (d0 >> 1)]     = pk(qv.x * sq, qv.y * sq);
        Qs[row * 36 + (d0 >> 1) + 1] = pk(qv.z * sq, qv.w * sq);
        float4 kk = *(const float4*)&g_k[gg];
        Ks[row * 36 + (d0 >> 1)]     = pk(kk.x * sk, kk.y * sk);
        Ks[row * 36 + (d0 >> 1) + 1] = pk(kk.z * sk, kk.w * sk);
        float4 vv = *(const float4*)&g_v[gg];
        Vt_h[(d0 + 0) * 136 + row] = __float2half_rn(vv.x);
        Vt_h[(d0 + 1) * 136 + row] = __float2half_rn(vv.y);
        Vt_h[(d0 + 2) * 136 + row] = __float2half_rn(vv.z);
        Vt_h[(d0 + 3) * 136 + row] = __float2half_rn(vv.w);
    }
    // Exclusive prefix over prior chunk states (fp32 accumulate, fp16 store)
    #pragma unroll
    for (int p = 0; p < 4; p++) {
        int slot = t + p * 256;               // 1024 float4 slots
        int m  = slot >> 4;
        int d0 = (slot & 15) << 2;
        float4 s = make_float4(0.0f, 0.0f, 0.0f, 0.0f);
        for (int c2 = 0; c2 < c; c2++) {
            float4 v = *(const float4*)&g_kv[((size_t)n * NC + c2) * HD * HD + m * HD + d0];
            s.x += v.x; s.y += v.y; s.z += v.z; s.w += v.w;
        }
        Pt[m * 36 + (d0 >> 1)]     = pk(s.x, s.y);
        Pt[m * 36 + (d0 >> 1) + 1] = pk(s.z, s.w);
    }
    __syncthreads();

    const int i0 = w * 16;
    const int r0 = i0 + g, r1 = i0 + g + 8;

    // Pass 1: S = causal(Q K^T)  (128x128, k=64 -> 4 k16 steps)
    {
        float acc1[16][4];
        #pragma unroll
        for (int nt = 0; nt < 16; nt++)
            #pragma unroll
            for (int q = 0; q < 4; q++) acc1[nt][q] = 0.0f;

        #pragma unroll
        for (int ks = 0; ks < 4; ks++) {
            int k8 = ks * 8;
            unsigned a[4];
            a[0] = Qs[r0 * 36 + k8 + tg];
            a[1] = Qs[r1 * 36 + k8 + tg];
            a[2] = Qs[r0 * 36 + k8 + tg + 4];
            a[3] = Qs[r1 * 36 + k8 + tg + 4];
            #pragma unroll
            for (int nt = 0; nt < 16; nt++) {
                unsigned bf[2];
                bf[0] = Ks[(nt * 8 + g) * 36 + k8 + tg];
                bf[1] = Ks[(nt * 8 + g) * 36 + k8 + tg + 4];
                mma_f16(acc1[nt], a, bf);
            }
        }
        #pragma unroll
        for (int nt = 0; nt < 16; nt++) {
            int j0 = nt * 8 + 2 * tg;
            Ss[r0 * 68 + nt * 4 + tg] = pk(j0 <= r0 ? acc1[nt][0] : 0.0f,
                                           j0 + 1 <= r0 ? acc1[nt][1] : 0.0f);
            Ss[r1 * 68 + nt * 4 + tg] = pk(j0 <= r1 ? acc1[nt][2] : 0.0f,
                                           j0 + 1 <= r1 ? acc1[nt][3] : 0.0f);
        }
    }
    __syncwarp();   // each warp reads only its own Ss rows

    // Pass 2: out = Q @ Pt + Ss @ Vt  (128x64)
    {
        float acc2[8][4];
        #pragma unroll
        for (int nt = 0; nt < 8; nt++)
            #pragma unroll
            for (int q = 0; q < 4; q++) acc2[nt][q] = 0.0f;

        #pragma unroll
        for (int ks = 0; ks < 4; ks++) {            // Q @ P, k = 64
            int k8 = ks * 8;
            unsigned a[4];
            a[0] = Qs[r0 * 36 + k8 + tg];
            a[1] = Qs[r1 * 36 + k8 + tg];
            a[2] = Qs[r0 * 36 + k8 + tg + 4];
            a[3] = Qs[r1 * 36 + k8 + tg + 4];
            #pragma unroll
            for (int nt = 0; nt < 8; nt++) {
                unsigned bf[2];
                bf[0] = Pt[(nt * 8 + g) * 36 + k8 + tg];
                bf[1] = Pt[(nt * 8 + g) * 36 + k8 + tg + 4];
                mma_f16(acc2[nt], a, bf);
            }
        }
        #pragma unroll
        for (int ks = 0; ks < 8; ks++) {            // S @ V, k = 128
            int k8 = ks * 8;
            unsigned a[4];
            a[0] = Ss[r0 * 68 + k8 + tg];
            a[1] = Ss[r1 * 68 + k8 + tg];
            a[2] = Ss[r0 * 68 + k8 + tg + 4];
            a[3] = Ss[r1 * 68 + k8 + tg + 4];
            #pragma unroll
            for (int nt = 0; nt < 8; nt++) {
                unsigned bf[2];
                bf[0] = Vt[(nt * 8 + g) * 68 + k8 + tg];
                bf[1] = Vt[(nt * 8 + g) * 68 + k8 + tg + 4];
                mma_f16(acc2[nt], a, bf);
            }
        }

        #pragma unroll
        for (int nt = 0; nt < 8; nt++) {
            int cc = nt * 8 + 2 * tg;
            int l0 = (c * CH + r0) * 2 + b;
            int l1 = (c * CH + r1) * 2 + b;
            *(float2*)&g_o[(size_t)l0 * EDIM + h * HD + cc] = make_float2(acc2[nt][0], acc2[nt][1]);
            *(float2*)&g_o[(size_t)l1 * EDIM + h * HD + cc] = make_float2(acc2[nt][2], acc2[nt][3]);
        }
    }
}

// ----------------------------------------------------------------------------
extern "C" void kernel_launch(void* const* d_in, const int* in_sizes, int n_in,
                              void* d_out, int out_size)
{
    const float* X  = (const float*)d_in[0];
    const float* Wq = (const float*)d_in[1];
    const float* bq = (const float*)d_in[2];
    const float* Wk = (const float*)d_in[3];
    const float* bk = (const float*)d_in[4];
    const float* Wv = (const float*)d_in[5];
    const float* bv = (const float*)d_in[6];
    const float* Wo = (const float*)d_in[7];
    const float* bo = (const float*)d_in[8];
    float* out = (float*)d_out;

    (void)in_sizes; (void)n_in; (void)out_size;

    cudaFuncSetAttribute(chunk_kv,   cudaFuncAttributeMaxDynamicSharedMemorySize, CHUNK_KV_SMEM);
    cudaFuncSetAttribute(chunk_attn, cudaFuncAttributeMaxDynamicSharedMemorySize, CHUNK_ATTN_SMEM);

    qkv_gemm<<<dim3(32, 4, 3), 256>>>(X, Wq, bq, Wk, bk, Wv, bv);
    norm_finalize<<<32, 256>>>();
    chunk_kv<<<dim3(NC, NH), 256, CHUNK_KV_SMEM>>>();
    chunk_attn<<<dim3(NC, NH), 256, CHUNK_ATTN_SMEM>>>();
    oproj_gemm<<<dim3(32, 4), 256>>>(Wo, bo, out);
}

// round 7
// speedup vs baseline: 1.5909x; 1.0537x over previous
#include <cuda_runtime.h>
#include <cuda_fp16.h>
#include <cstdint>

// Problem constants
#define EDIM   512
#define NROWS  4096      // B*L = 2*2048 (flat rows)
#define CH     128       // attention chunk length
#define NC     16        // LSEQ / CH
#define NH     16        // B * n_head = 2*8
#define HD     64        // head dim

// Scratch (device globals: no allocations allowed)
__device__ float g_q[NROWS * EDIM];
__device__ float g_k[NROWS * EDIM];
__device__ float g_v[NROWS * EDIM];
__device__ float g_o[NROWS * EDIM];
__device__ float g_kv[NH * NC * HD * HD];   // per-chunk KV states, stored as ST[m][d]
__device__ float g_sumsq_q[NROWS * 4];      // per (row, colTile) partial sum of squares
__device__ float g_sumsq_k[NROWS * 4];
__device__ int   g_ready[NH * NC];          // chunk-state ready flags

// ----------------------------------------------------------------------------
// fp16 helpers
// ----------------------------------------------------------------------------
__device__ __forceinline__ unsigned pk(float x, float y) {
    __half2 h = __floats2half2_rn(x, y);
    return *(unsigned*)&h;
}

__device__ __forceinline__ void mma_f16(float* c, const unsigned* a, const unsigned* b) {
    asm volatile(
        "mma.sync.aligned.m16n8k16.row.col.f32.f16.f16.f32 "
        "{%0,%1,%2,%3}, {%4,%5,%6,%7}, {%8,%9}, {%0,%1,%2,%3};"
        : "+f"(c[0]), "+f"(c[1]), "+f"(c[2]), "+f"(c[3])
        : "r"(a[0]), "r"(a[1]), "r"(a[2]), "r"(a[3]), "r"(b[0]), "r"(b[1]));
}

// ----------------------------------------------------------------------------
// fp16 tensor-core GEMM (NT): C[i][j] = act( sum_e A[i][e] * W[j][e] + bias[j] )
// Block tile 128x128, K-tile 32 (2 x k16 steps), 256 threads = 8 warps,
// warp tile 64x32, register-staged single-smem-buffer pipeline.
// Epilogue: bias + relu + deterministic per-row sumsq partials (sel 0/1).
// ----------------------------------------------------------------------------
__device__ __forceinline__ void gemm_body(
    const float* __restrict__ A, const float* __restrict__ W,
    const float* __restrict__ bias, float* __restrict__ C,
    int rowBase, int colBase, bool relu, int sel)
{
    __shared__ unsigned As[128 * 20];
    __shared__ unsigned Bs[128 * 20];

    const int t    = threadIdx.x;
    const int lane = t & 31;
    const int warp = t >> 5;
    const int wm   = (warp >> 2) * 64;
    const int wn   = (warp & 3) * 32;
    const int g    = lane >> 2;
    const int tg   = lane & 3;

    float acc[4][4][4];
    #pragma unroll
    for (int mt = 0; mt < 4; mt++)
        #pragma unroll
        for (int nt = 0; nt < 4; nt++)
            #pragma unroll
            for (int q = 0; q < 4; q++) acc[mt][nt][q] = 0.0f;

    float4 stA[4], stB[4];

    #pragma unroll
    for (int p = 0; p < 4; p++) {
        int idx = t + p * 256;
        int r   = idx >> 3;
        int kq  = (idx & 7) << 2;
        stA[p] = *(const float4*)&A[(size_t)(rowBase + r) * EDIM + kq];
        stB[p] = *(const float4*)&W[(size_t)(colBase + r) * EDIM + kq];
    }
    #pragma unroll
    for (int p = 0; p < 4; p++) {
        int idx = t + p * 256;
        int r   = idx >> 3;
        int c2  = (idx & 7) << 1;
        As[r * 20 + c2]     = pk(stA[p].x, stA[p].y);
        As[r * 20 + c2 + 1] = pk(stA[p].z, stA[p].w);
        Bs[r * 20 + c2]     = pk(stB[p].x, stB[p].y);
        Bs[r * 20 + c2 + 1] = pk(stB[p].z, stB[p].w);
    }
    __syncthreads();

    for (int it = 0; it < EDIM / 32; it++) {
        const bool has_next = (it + 1 < EDIM / 32);
        if (has_next) {
            int k0 = (it + 1) * 32;
            #pragma unroll
            for (int p = 0; p < 4; p++) {
                int idx = t + p * 256;
                int r   = idx >> 3;
                int kq  = (idx & 7) << 2;
                stA[p] = *(const float4*)&A[(size_t)(rowBase + r) * EDIM + k0 + kq];
                stB[p] = *(const float4*)&W[(size_t)(colBase + r) * EDIM + k0 + kq];
            }
        }

        #pragma unroll
        for (int ks = 0; ks < 2; ks++) {
            const int k8 = ks * 8;
            unsigned af[4][4], bf[4][2];
            #pragma unroll
            for (int mt = 0; mt < 4; mt++) {
                int row = wm + mt * 16 + g;
                af[mt][0] = As[row * 20 + k8 + tg];
                af[mt][1] = As[(row + 8) * 20 + k8 + tg];
                af[mt][2] = As[row * 20 + k8 + tg + 4];
                af[mt][3] = As[(row + 8) * 20 + k8 + tg + 4];
            }
            #pragma unroll
            for (int nt = 0; nt < 4; nt++) {
                int nr = wn + nt * 8 + g;
                bf[nt][0] = Bs[nr * 20 + k8 + tg];
                bf[nt][1] = Bs[nr * 20 + k8 + tg + 4];
            }
            #pragma unroll
            for (int mt = 0; mt < 4; mt++)
                #pragma unroll
                for (int nt = 0; nt < 4; nt++)
                    mma_f16(acc[mt][nt], af[mt], bf[nt]);
        }

        if (has_next) {
            __syncthreads();
            #pragma unroll
            for (int p = 0; p < 4; p++) {
                int idx = t + p * 256;
                int r   = idx >> 3;
                int c2  = (idx & 7) << 1;
                As[r * 20 + c2]     = pk(stA[p].x, stA[p].y);
                As[r * 20 + c2 + 1] = pk(stA[p].z, stA[p].w);
                Bs[r * 20 + c2]     = pk(stB[p].x, stB[p].y);
                Bs[r * 20 + c2 + 1] = pk(stB[p].z, stB[p].w);
            }
            __syncthreads();
        }
    }

    float ssr0[4], ssr1[4];
    #pragma unroll
    for (int mt = 0; mt < 4; mt++) { ssr0[mt] = 0.0f; ssr1[mt] = 0.0f; }

    #pragma unroll
    for (int nt = 0; nt < 4; nt++) {
        int cc = colBase + wn + nt * 8 + 2 * tg;
        float bx = bias[cc], by = bias[cc + 1];
        #pragma unroll
        for (int mt = 0; mt < 4; mt++) {
            int r0 = rowBase + wm + mt * 16 + g;
            float2 v0, v1;
            v0.x = acc[mt][nt][0] + bx; v0.y = acc[mt][nt][1] + by;
            v1.x = acc[mt][nt][2] + bx; v1.y = acc[mt][nt][3] + by;
            if (relu) {
                v0.x = fmaxf(v0.x, 0.0f); v0.y = fmaxf(v0.y, 0.0f);
                v1.x = fmaxf(v1.x, 0.0f); v1.y = fmaxf(v1.y, 0.0f);
            }
            ssr0[mt] += v0.x * v0.x + v0.y * v0.y;
            ssr1[mt] += v1.x * v1.x + v1.y * v1.y;
            *(float2*)&C[(size_t)r0 * EDIM + cc]       = v0;
            *(float2*)&C[(size_t)(r0 + 8) * EDIM + cc] = v1;
        }
    }

    if (sel <= 1) {
        #pragma unroll
        for (int mt = 0; mt < 4; mt++) {
            #pragma unroll
            for (int o = 1; o < 4; o <<= 1) {
                ssr0[mt] += __shfl_xor_sync(0xffffffffu, ssr0[mt], o);
                ssr1[mt] += __shfl_xor_sync(0xffffffffu, ssr1[mt], o);
            }
        }
        __syncthreads();
        float* red = (float*)As;
        if (tg == 0) {
            #pragma unroll
            for (int mt = 0; mt < 4; mt++) {
                int rl = wm + mt * 16 + g;
                red[(warp & 3) * 128 + rl]     = ssr0[mt];
                red[(warp & 3) * 128 + rl + 8] = ssr1[mt];
            }
        }
        __syncthreads();
        if (t < 128) {
            float s = red[t] + red[128 + t] + red[256 + t] + red[384 + t];
            float* dst = (sel == 0) ? g_sumsq_q : g_sumsq_k;
            dst[(rowBase + t) * 4 + (colBase >> 7)] = s;
        }
    }
}

__global__ void __launch_bounds__(256) qkv_gemm(
    const float* __restrict__ X,
    const float* __restrict__ Wq, const float* __restrict__ bq,
    const float* __restrict__ Wk, const float* __restrict__ bk,
    const float* __restrict__ Wv, const float* __restrict__ bv)
{
    // Reset chunk-state flags each replay (stream-ordered before chunk_attn).
    if (blockIdx.x == 0 && blockIdx.y == 0 && blockIdx.z == 0 && threadIdx.x < NH * NC)
        g_ready[threadIdx.x] = 0;

    int rowBase = blockIdx.x * 128;
    int colBase = blockIdx.y * 128;
    int which   = blockIdx.z;
    if (which == 0)      gemm_body(X, Wq, bq, g_q, rowBase, colBase, true, 0);
    else if (which == 1) gemm_body(X, Wk, bk, g_k, rowBase, colBase, true, 1);
    else                 gemm_body(X, Wv, bv, g_v, rowBase, colBase, false, 2);
}

__global__ void __launch_bounds__(256) oproj_gemm(
    const float* __restrict__ Wo, const float* __restrict__ bo,
    float* __restrict__ out)
{
    gemm_body(g_o, Wo, bo, out, blockIdx.x * 128, blockIdx.y * 128, false, 2);
}

// ----------------------------------------------------------------------------
// Fused attention: per (chunk c, head n):
//   phase 0: row scales from g_sumsq
//   phase 1: load Q,K (scaled, fp16) + K^T + V^T tiles
//   phase 2: S_c = V^T K -> g_kv ; release flag
//   phase 3: wait flags c2<c ; P = sum S_c2 (fp32) -> Pt fp16
//   phase 4: S = causal(Q K^T) with masked-tile skipping (warp-balanced)
//   phase 5: out = Q @ P + S @ V
// smem (words): Qs 4608 | Ks 4608 | Vt 4352 | Pt 2304 | Ss 8704 (Kt aliases) | scales 256
// ----------------------------------------------------------------------------
#define ATTN_W_QS 0
#define ATTN_W_KS 4608
#define ATTN_W_VT 9216
#define ATTN_W_PT 13568
#define ATTN_W_SS 15872
#define ATTN_W_SC 24576
#define CHUNK_ATTN_SMEM ((24576 + 256) * 4)

__global__ void __launch_bounds__(256, 2) chunk_attn()
{
    int c = blockIdx.x, n = blockIdx.y;
    int b = n >> 3, h = n & 7;
    extern __shared__ unsigned smu[];
    unsigned* Qs = smu + ATTN_W_QS;         // [128][36] h2
    unsigned* Ks = smu + ATTN_W_KS;         // [128][36] h2
    unsigned* Vt = smu + ATTN_W_VT;         // [64][68] h2 (transposed)
    unsigned* Pt = smu + ATTN_W_PT;         // [64][36] h2
    unsigned* Ss = smu + ATTN_W_SS;         // [128][68] h2
    unsigned* Kt = Ss;                      // [64][68] h2 alias (dead before pass1)
    float* ks_s  = (float*)(smu + ATTN_W_SC);
    float* qs_s  = ks_s + 128;
    __half* Vt_h = (__half*)Vt;
    __half* Kt_h = (__half*)Kt;
    int t = threadIdx.x;
    int lane = t & 31, w = t >> 5;
    int g = lane >> 2, tg = lane & 3;

    // phase 0: per-row reciprocal norms
    {
        int row = t & 127;
        int rr  = (c * CH + row) * 2 + b;
        const float* s = ((t < 128) ? g_sumsq_k : g_sumsq_q) + rr * 4;
        float sc = 1.0f / fmaxf(sqrtf(s[0] + s[1] + s[2] + s[3]), 1e-12f);
        ((t < 128) ? ks_s : qs_s)[row] = sc;
    }
    __syncthreads();

    // phase 1: tile loads
    #pragma unroll
    for (int p = 0; p < 8; p++) {
        int idx = t + p * 256;
        int row = idx >> 4;
        int d0  = (idx & 15) << 2;
        int rr  = (c * CH + row) * 2 + b;
        size_t gg = (size_t)rr * EDIM + h * HD + d0;
        float sq = qs_s[row];
        float sk = ks_s[row];
        float4 qv = *(const float4*)&g_q[gg];
        Qs[row * 36 + (d0 >> 1)]     = pk(qv.x * sq, qv.y * sq);
        Qs[row * 36 + (d0 >> 1) + 1] = pk(qv.z * sq, qv.w * sq);
        float4 kk = *(const float4*)&g_k[gg];
        float kx = kk.x * sk, ky = kk.y * sk, kz = kk.z * sk, kw = kk.w * sk;
        Ks[row * 36 + (d0 >> 1)]     = pk(kx, ky);
        Ks[row * 36 + (d0 >> 1) + 1] = pk(kz, kw);
        Kt_h[(d0 + 0) * 136 + row] = __float2half_rn(kx);
        Kt_h[(d0 + 1) * 136 + row] = __float2half_rn(ky);
        Kt_h[(d0 + 2) * 136 + row] = __float2half_rn(kz);
        Kt_h[(d0 + 3) * 136 + row] = __float2half_rn(kw);
        float4 vv = *(const float4*)&g_v[gg];
        Vt_h[(d0 + 0) * 136 + row] = __float2half_rn(vv.x);
        Vt_h[(d0 + 1) * 136 + row] = __float2half_rn(vv.y);
        Vt_h[(d0 + 2) * 136 + row] = __float2half_rn(vv.z);
        Vt_h[(d0 + 3) * 136 + row] = __float2half_rn(vv.w);
    }
    __syncthreads();

    // phase 2: S_c[m][d] = sum_j V[j][m] * K[j][d]
    {
        int m0 = (w & 3) * 16;
        int nb = (w >> 2) * 32;
        float acc[4][4];
        #pragma unroll
        for (int i = 0; i < 4; i++)
            #pragma unroll
            for (int j = 0; j < 4; j++) acc[i][j] = 0.0f;

        #pragma unroll
        for (int ks = 0; ks < 8; ks++) {
            int k8 = ks * 8;
            unsigned a[4];
            a[0] = Vt[(m0 + g) * 68 + k8 + tg];
            a[1] = Vt[(m0 + g + 8) * 68 + k8 + tg];
            a[2] = Vt[(m0 + g) * 68 + k8 + tg + 4];
            a[3] = Vt[(m0 + g + 8) * 68 + k8 + tg + 4];
            #pragma unroll
            for (int nt = 0; nt < 4; nt++) {
                unsigned bf[2];
                bf[0] = Kt[(nb + nt * 8 + g) * 68 + k8 + tg];
                bf[1] = Kt[(nb + nt * 8 + g) * 68 + k8 + tg + 4];
                mma_f16(acc[nt], a, bf);
            }
        }
        float* outp = &g_kv[((size_t)n * NC + c) * HD * HD];
        #pragma unroll
        for (int nt = 0; nt < 4; nt++) {
            int cc = nb + nt * 8 + 2 * tg;
            *(float2*)&outp[(m0 + g) * HD + cc]     = make_float2(acc[nt][0], acc[nt][1]);
            *(float2*)&outp[(m0 + g + 8) * HD + cc] = make_float2(acc[nt][2], acc[nt][3]);
        }
    }
    __threadfence();
    __syncthreads();
    if (t == 0) atomicExch(&g_ready[n * NC + c], 1);

    // phase 3: wait for prior chunks, sum prefix (fp32 -> fp16)
    if (t < c) {
        while (atomicAdd(&g_ready[n * NC + t], 0) == 0) { }
    }
    __syncthreads();
    __threadfence();
    #pragma unroll
    for (int p = 0; p < 4; p++) {
        int slot = t + p * 256;
        int m  = slot >> 4;
        int d0 = (slot & 15) << 2;
        float4 s = make_float4(0.0f, 0.0f, 0.0f, 0.0f);
        for (int c2 = 0; c2 < c; c2++) {
            float4 v = *(const float4*)&g_kv[((size_t)n * NC + c2) * HD * HD + m * HD + d0];
            s.x += v.x; s.y += v.y; s.z += v.z; s.w += v.w;
        }
        Pt[m * 36 + (d0 >> 1)]     = pk(s.x, s.y);
        Pt[m * 36 + (d0 >> 1) + 1] = pk(s.z, s.w);
    }
    __syncthreads();   // Pt ready; Kt region now dead -> pass1 may write Ss

    // Warp-balanced causal row-block assignment
    const int rb = (w < 4) ? w : 11 - w;
    const int i0 = rb * 16;
    const int r0 = i0 + g, r1 = i0 + g + 8;
    const int ntmax = 2 * rb + 1;

    // phase 4: S = causal(Q K^T), only non-fully-masked tiles
    {
        float acc1[16][4];
        #pragma unroll
        for (int nt = 0; nt < 16; nt++)
            #pragma unroll
            for (int q = 0; q < 4; q++) acc1[nt][q] = 0.0f;

        #pragma unroll
        for (int ks = 0; ks < 4; ks++) {
            int k8 = ks * 8;
            unsigned a[4];
            a[0] = Qs[r0 * 36 + k8 + tg];
            a[1] = Qs[r1 * 36 + k8 + tg];
            a[2] = Qs[r0 * 36 + k8 + tg + 4];
            a[3] = Qs[r1 * 36 + k8 + tg + 4];
            #pragma unroll
            for (int nt = 0; nt < 16; nt++) {
                if (nt <= ntmax) {
                    unsigned bf[2];
                    bf[0] = Ks[(nt * 8 + g) * 36 + k8 + tg];
                    bf[1] = Ks[(nt * 8 + g) * 36 + k8 + tg + 4];
                    mma_f16(acc1[nt], a, bf);
                }
            }
        }
        #pragma unroll
        for (int nt = 0; nt < 16; nt++) {
            if (nt <= ntmax) {
                int j0 = nt * 8 + 2 * tg;
                Ss[r0 * 68 + nt * 4 + tg] = pk(j0 <= r0 ? acc1[nt][0] : 0.0f,
                                               j0 + 1 <= r0 ? acc1[nt][1] : 0.0f);
                Ss[r1 * 68 + nt * 4 + tg] = pk(j0 <= r1 ? acc1[nt][2] : 0.0f,
                                               j0 + 1 <= r1 ? acc1[nt][3] : 0.0f);
            }
        }
    }
    __syncwarp();   // each warp reads only its own Ss rows

    // phase 5: out = Q @ Pt + Ss @ Vt
    {
        float acc2[8][4];
        #pragma unroll
        for (int nt = 0; nt < 8; nt++)
            #pragma unroll
            for (int q = 0; q < 4; q++) acc2[nt][q] = 0.0f;

        #pragma unroll
        for (int ks = 0; ks < 4; ks++) {            // Q @ P, k = 64
            int k8 = ks * 8;
            unsigned a[4];
            a[0] = Qs[r0 * 36 + k8 + tg];
            a[1] = Qs[r1 * 36 + k8 + tg];
            a[2] = Qs[r0 * 36 + k8 + tg + 4];
            a[3] = Qs[r1 * 36 + k8 + tg + 4];
            #pragma unroll
            for (int nt = 0; nt < 8; nt++) {
                unsigned bf[2];
                bf[0] = Pt[(nt * 8 + g) * 36 + k8 + tg];
                bf[1] = Pt[(nt * 8 + g) * 36 + k8 + tg + 4];
                mma_f16(acc2[nt], a, bf);
            }
        }
        #pragma unroll
        for (int ks = 0; ks < 8; ks++) {            // S @ V, k <= (rb+1)*16
            if (ks <= rb) {
                int k8 = ks * 8;
                unsigned a[4];
                a[0] = Ss[r0 * 68 + k8 + tg];
                a[1] = Ss[r1 * 68 + k8 + tg];
                a[2] = Ss[r0 * 68 + k8 + tg + 4];
                a[3] = Ss[r1 * 68 + k8 + tg + 4];
                #pragma unroll
                for (int nt = 0; nt < 8; nt++) {
                    unsigned bf[2];
                    bf[0] = Vt[(nt * 8 + g) * 68 + k8 + tg];
                    bf[1] = Vt[(nt * 8 + g) * 68 + k8 + tg + 4];
                    mma_f16(acc2[nt], a, bf);
                }
            }
        }

        #pragma unroll
        for (int nt = 0; nt < 8; nt++) {
            int cc = nt * 8 + 2 * tg;
            int l0 = (c * CH + r0) * 2 + b;
            int l1 = (c * CH + r1) * 2 + b;
            *(float2*)&g_o[(size_t)l0 * EDIM + h * HD + cc] = make_float2(acc2[nt][0], acc2[nt][1]);
            *(float2*)&g_o[(size_t)l1 * EDIM + h * HD + cc] = make_float2(acc2[nt][2], acc2[nt][3]);
        }
    }
}

// ----------------------------------------------------------------------------
extern "C" void kernel_launch(void* const* d_in, const int* in_sizes, int n_in,
                              void* d_out, int out_size)
{
    const float* X  = (const float*)d_in[0];
    const float* Wq = (const float*)d_in[1];
    const float* bq = (const float*)d_in[2];
    const float* Wk = (const float*)d_in[3];
    const float* bk = (const float*)d_in[4];
    const float* Wv = (const float*)d_in[5];
    const float* bv = (const float*)d_in[6];
    const float* Wo = (const float*)d_in[7];
    const float* bo = (const float*)d_in[8];
    float* out = (float*)d_out;

    (void)in_sizes; (void)n_in; (void)out_size;

    cudaFuncSetAttribute(chunk_attn, cudaFuncAttributeMaxDynamicSharedMemorySize, CHUNK_ATTN_SMEM);

    qkv_gemm<<<dim3(32, 4, 3), 256>>>(X, Wq, bq, Wk, bk, Wv, bv);
    chunk_attn<<<dim3(NC, NH), 256, CHUNK_ATTN_SMEM>>>();
    oproj_gemm<<<dim3(32, 4), 256>>>(Wo, bo, out);
}